// round 5
// baseline (speedup 1.0000x reference)
#include <cuda_runtime.h>

#define BATCH 16
#define IMG_H 1024
#define IMG_W 1024
#define WPR   32                 // 32-bit words per row (1024/32)
#define NROWS (BATCH * IMG_H)
#define NTOT  ((double)BATCH * IMG_H * IMG_W)
#define ROWS_PER_BLK 8
#define NBLK  (NROWS / 8)        // 2048 main-kernel blocks

// Scratch (allocation-free: __device__ globals)
__device__ unsigned int g_lbits[NROWS * WPR];   // label bits, 2 MB
__device__ unsigned int g_hbits[NROWS * WPR];   // horizontal-OR (r=7) bits, 2 MB
// Per-block partials (no contended atomics anywhere)
__device__ float g_pAll[NBLK];
__device__ float g_pEdge[NBLK];
__device__ float g_pLab[NBLK];
__device__ int   g_cLab[NBLK];
__device__ int   g_cEdge[NBLK];

// ---------------------------------------------------------------------------
// Kernel A: 256 threads / 8 rows. All 8 int4 loads batched up front (MLP=8),
// labels are 0/1 so nibble = v.x | v.y<<1 | v.z<<2 | v.w<<3. Shuffle-fold to
// 32-bit words, then horizontal radius-7 OR via 64-bit shift doubling.
// ---------------------------------------------------------------------------
__global__ void __launch_bounds__(256) pack_hor(const int* __restrict__ label) {
    __shared__ unsigned int sw[ROWS_PER_BLK * WPR];
    const int t    = threadIdx.x;
    const int lane = t & 31;

    const int4* lab4 = (const int4*)label + (size_t)blockIdx.x * (ROWS_PER_BLK * WPR * 8);
    int4 v[8];
#pragma unroll
    for (int k = 0; k < 8; k++) v[k] = lab4[k * 256 + t];

#pragma unroll
    for (int k = 0; k < 8; k++) {
        unsigned int nib = (unsigned)v[k].x | ((unsigned)v[k].y << 1)
                         | ((unsigned)v[k].z << 2) | ((unsigned)v[k].w << 3);
        unsigned int val = nib << (4 * (lane & 7));
        val |= __shfl_xor_sync(0xffffffffu, val, 1);
        val |= __shfl_xor_sync(0xffffffffu, val, 2);
        val |= __shfl_xor_sync(0xffffffffu, val, 4);
        if ((lane & 7) == 0) sw[(k * 256 + t) >> 3] = val;
    }
    __syncthreads();

    const int w = t & 31;
    const unsigned int wl = (w > 0)       ? sw[t - 1] : 0u;
    const unsigned int wc = sw[t];
    const unsigned int wr = (w < WPR - 1) ? sw[t + 1] : 0u;
    unsigned long long a = (unsigned long long)wc | ((unsigned long long)wr << 32);
    a |= a >> 1; a |= a >> 2; a |= a >> 4;              // OR of px x..x+7
    unsigned long long c = (unsigned long long)wl | ((unsigned long long)wc << 32);
    c |= c << 1; c |= c << 2; c |= c << 4;              // OR of px x-7..x
    const size_t gidx = (size_t)blockIdx.x * (ROWS_PER_BLK * WPR) + t;
    g_lbits[gidx] = wc;
    g_hbits[gidx] = (unsigned int)a | (unsigned int)(c >> 32);
}

// ---------------------------------------------------------------------------
// Kernel B: 8 warps / 8 rows per block. Pred loads batched first (MLP=8),
// reg-resident. Vertical OR via smem; masks pre-transposed. Per-block
// partials written with plain STG to distinct slots — NO global atomics.
// ---------------------------------------------------------------------------
__global__ void __launch_bounds__(256) main_kernel(const float* __restrict__ Pred) {
    __shared__ unsigned int se[22 * WPR];               // hbits rows y0-7 .. y0+14
    const int t    = threadIdx.x;
    const int lane = t & 31;
    const int wid  = t >> 5;
    const int row0 = blockIdx.x * 8;
    const int y0   = row0 & (IMG_H - 1);
    const int imgbase = row0 - y0;
    const int row  = row0 + wid;

    // 1) Pred: 8 front-batched coalesced LDG.128 (512B/warp each)
    const float4* prow = (const float4*)(Pred + (size_t)row * IMG_W);
    float4 p[8];
#pragma unroll
    for (int k = 0; k < 8; k++) p[k] = prow[k * 32 + lane];

    // 2) Cooperative smem fill: 22 clipped hbits rows (704 words)
    for (int i = t; i < 22 * WPR; i += 256) {
        const int yy = y0 - 7 + (i >> 5);
        unsigned int v = 0;
        if (yy >= 0 && yy < IMG_H)
            v = g_hbits[(size_t)(imgbase + yy) * WPR + (i & 31)];
        se[i] = v;
    }
    const unsigned int lw = g_lbits[(size_t)row * WPR + lane];
    __syncthreads();

    // 3) Vertical OR from smem
    unsigned int ew = 0;
#pragma unroll
    for (int dy = 0; dy < 15; dy++) ew |= se[(wid + dy) * WPR + lane];

    int cLab  = __popc(lw);
    int cEdge = __popc(ew);

    // 4) Transpose: lane's pixel i (=4k+j) is word 4k+(lane>>3), nib 4*(lane&7)
    unsigned int mylw = 0, myew = 0;
    const int nsh = 4 * (lane & 7);
#pragma unroll
    for (int k = 0; k < 8; k++) {
        const int widx = 4 * k + (lane >> 3);
        mylw |= ((__shfl_sync(0xffffffffu, lw, widx) >> nsh) & 0xFu) << (4 * k);
        myew |= ((__shfl_sync(0xffffffffu, ew, widx) >> nsh) & 0xFu) << (4 * k);
    }

    // 5) Compute: reg-resident, split accumulators
    float sAll0 = 0.f, sEdge0 = 0.f, sLab0 = 0.f;
    float sAll1 = 0.f, sEdge1 = 0.f, sLab1 = 0.f;

#define PIX(pv, bit, sA, sE, sL)                                   \
    {                                                              \
        const bool tl = (mylw >> (bit)) & 1u;                      \
        const bool el = (myew >> (bit)) & 1u;                      \
        const float q  = tl ? (pv) : 1.0f - (pv);                  \
        const float l2 = __log2f(q);                               \
        sA += l2;                                                  \
        if (el) sE += l2;                                          \
        if (tl) sL += l2;                                          \
    }

#pragma unroll
    for (int k = 0; k < 8; k += 2) {
        PIX(p[k].x,     4 * k + 0, sAll0, sEdge0, sLab0)
        PIX(p[k].y,     4 * k + 1, sAll0, sEdge0, sLab0)
        PIX(p[k].z,     4 * k + 2, sAll0, sEdge0, sLab0)
        PIX(p[k].w,     4 * k + 3, sAll0, sEdge0, sLab0)
        PIX(p[k + 1].x, 4 * k + 4, sAll1, sEdge1, sLab1)
        PIX(p[k + 1].y, 4 * k + 5, sAll1, sEdge1, sLab1)
        PIX(p[k + 1].z, 4 * k + 6, sAll1, sEdge1, sLab1)
        PIX(p[k + 1].w, 4 * k + 7, sAll1, sEdge1, sLab1)
    }
#undef PIX

    float sAll = sAll0 + sAll1, sEdge = sEdge0 + sEdge1, sLab = sLab0 + sLab1;

#pragma unroll
    for (int off = 16; off; off >>= 1) {
        sAll  += __shfl_xor_sync(0xffffffffu, sAll,  off);
        sEdge += __shfl_xor_sync(0xffffffffu, sEdge, off);
        sLab  += __shfl_xor_sync(0xffffffffu, sLab,  off);
    }
    cLab  = __reduce_add_sync(0xffffffffu, cLab);
    cEdge = __reduce_add_sync(0xffffffffu, cEdge);

    __shared__ float fs[3][8];
    __shared__ int   is[2][8];
    if (lane == 0) {
        fs[0][wid] = sAll; fs[1][wid] = sEdge; fs[2][wid] = sLab;
        is[0][wid] = cLab; is[1][wid] = cEdge;
    }
    __syncthreads();
    if (t == 0) {
        float bA = 0, bE = 0, bL = 0; int iL = 0, iE = 0;
#pragma unroll
        for (int i = 0; i < 8; i++) {
            bA += fs[0][i]; bE += fs[1][i]; bL += fs[2][i];
            iL += is[0][i]; iE += is[1][i];
        }
        g_pAll[blockIdx.x]  = bA;        // plain stores, distinct addresses
        g_pEdge[blockIdx.x] = bE;
        g_pLab[blockIdx.x]  = bL;
        g_cLab[blockIdx.x]  = iL;
        g_cEdge[blockIdx.x] = iE;
    }
}

// ---------------------------------------------------------------------------
// Kernel C: 1 block, 1024 threads — reduce 2048 partials, emit scalar.
// ---------------------------------------------------------------------------
__global__ void __launch_bounds__(1024) finalize(float* __restrict__ out) {
    const int t    = threadIdx.x;
    const int lane = t & 31;
    const int wid  = t >> 5;

    double a = 0, e = 0, l = 0; int iL = 0, iE = 0;
#pragma unroll
    for (int k = 0; k < 2; k++) {
        const int i = k * 1024 + t;
        a += (double)g_pAll[i];
        e += (double)g_pEdge[i];
        l += (double)g_pLab[i];
        iL += g_cLab[i];
        iE += g_cEdge[i];
    }
#pragma unroll
    for (int off = 16; off; off >>= 1) {
        a += __shfl_xor_sync(0xffffffffu, a, off);
        e += __shfl_xor_sync(0xffffffffu, e, off);
        l += __shfl_xor_sync(0xffffffffu, l, off);
    }
    iL = __reduce_add_sync(0xffffffffu, iL);
    iE = __reduce_add_sync(0xffffffffu, iE);

    __shared__ double ds[3][32];
    __shared__ int    dsi[2][32];
    if (lane == 0) {
        ds[0][wid] = a; ds[1][wid] = e; ds[2][wid] = l;
        dsi[0][wid] = iL; dsi[1][wid] = iE;
    }
    __syncthreads();
    if (t == 0) {
        double sA = 0, sE2 = 0, sL = 0; double nL = 0, nE = 0;
#pragma unroll
        for (int i = 0; i < 32; i++) {
            sA += ds[0][i]; sE2 += ds[1][i]; sL += ds[2][i];
            nL += (double)dsi[0][i]; nE += (double)dsi[1][i];
        }
        const double N  = NTOT;
        const double wE = (1.0 - nL / N) * 1.0;
        const double wB = (1.0 - (nE - nL) / N) * 0.8;
        const double wT = (1.0 - (N - nE) / N) * 0.5;
        const double LN2 = 0.6931471805599453;
        out[0] = (float)(-LN2 * (wE * sL + wB * (sE2 - sL) + wT * (sA - sE2)) / N);
    }
}

extern "C" void kernel_launch(void* const* d_in, const int* in_sizes, int n_in,
                              void* d_out, int out_size) {
    const float* Pred  = (const float*)d_in[0];
    const int*   label = (const int*)d_in[1];
    (void)in_sizes; (void)n_in; (void)out_size;

    pack_hor<<<NROWS / ROWS_PER_BLK, 256>>>(label);
    main_kernel<<<NBLK, 256>>>(Pred);
    finalize<<<1, 1024>>>((float*)d_out);
}

// round 6
// speedup vs baseline: 1.1412x; 1.1412x over previous
#include <cuda_runtime.h>

#define BATCH 16
#define IMG_H 1024
#define IMG_W 1024
#define WPR   32                 // 32-bit words per row (1024/32)
#define NROWS (BATCH * IMG_H)
#define NTOT  ((double)BATCH * IMG_H * IMG_W)
#define ROWS_PER_BLK 8

// Scratch (allocation-free: __device__ globals)
__device__ unsigned int g_lbits[NROWS * WPR];   // label bits, 2 MB
__device__ unsigned int g_hbits[NROWS * WPR];   // horizontal-OR (r=7) bits, 2 MB
__device__ double g_sum[3];                     // sums of lg2(q): All, Edge, Lab
__device__ int    g_cnt[2];                     // counts: Lab, Edge
__device__ int    g_done;                       // arrival counter (reset each run)

// ---------------------------------------------------------------------------
// Kernel A: 256 threads / 8 rows. Chunked int4 loads (unroll 4 -> modest MLP,
// low reg pressure, high occupancy). Shuffle-fold to 32-bit words, then
// horizontal radius-7 OR via 64-bit shift doubling.
// ---------------------------------------------------------------------------
__global__ void __launch_bounds__(256) pack_hor(const int* __restrict__ label) {
    __shared__ unsigned int sw[ROWS_PER_BLK * WPR];
    const int t    = threadIdx.x;
    const int lane = t & 31;

    if (blockIdx.x == 0 && t < 3) {
        g_sum[t] = 0.0;
        if (t < 2) g_cnt[t] = 0;
    }

    const int4* lab4 = (const int4*)label + (size_t)blockIdx.x * (ROWS_PER_BLK * WPR * 8);

#pragma unroll 4
    for (int k = 0; k < 8; k++) {
        const int4 v = lab4[k * 256 + t];
        unsigned int nib = (unsigned)v.x | ((unsigned)v.y << 1)
                         | ((unsigned)v.z << 2) | ((unsigned)v.w << 3);
        unsigned int val = nib << (4 * (lane & 7));
        val |= __shfl_xor_sync(0xffffffffu, val, 1);
        val |= __shfl_xor_sync(0xffffffffu, val, 2);
        val |= __shfl_xor_sync(0xffffffffu, val, 4);
        if ((lane & 7) == 0) sw[(k * 256 + t) >> 3] = val;
    }
    __syncthreads();

    const int w = t & 31;
    const unsigned int wl = (w > 0)       ? sw[t - 1] : 0u;
    const unsigned int wc = sw[t];
    const unsigned int wr = (w < WPR - 1) ? sw[t + 1] : 0u;
    unsigned long long a = (unsigned long long)wc | ((unsigned long long)wr << 32);
    a |= a >> 1; a |= a >> 2; a |= a >> 4;              // OR of px x..x+7
    unsigned long long c = (unsigned long long)wl | ((unsigned long long)wc << 32);
    c |= c << 1; c |= c << 2; c |= c << 4;              // OR of px x-7..x
    const size_t gidx = (size_t)blockIdx.x * (ROWS_PER_BLK * WPR) + t;
    g_lbits[gidx] = wc;
    g_hbits[gidx] = (unsigned int)a | (unsigned int)(c >> 32);
}

// ---------------------------------------------------------------------------
// Kernel B: 8 warps / 8 rows per block. CHUNKED Pred loads (unroll 4) keep
// register pressure low -> high occupancy -> latency hidden by warps, not by
// per-thread batching. Vertical OR via smem; masks pre-transposed. Fused
// atomic finish + last-block finalize.
// ---------------------------------------------------------------------------
__global__ void __launch_bounds__(256) main_kernel(const float* __restrict__ Pred,
                                                   float* __restrict__ out) {
    __shared__ unsigned int se[22 * WPR];               // hbits rows y0-7 .. y0+14
    const int t    = threadIdx.x;
    const int lane = t & 31;
    const int wid  = t >> 5;
    const int row0 = blockIdx.x * 8;
    const int y0   = row0 & (IMG_H - 1);
    const int imgbase = row0 - y0;
    const int row  = row0 + wid;

    // Cooperative smem fill: 22 clipped hbits rows (704 words)
    for (int i = t; i < 22 * WPR; i += 256) {
        const int yy = y0 - 7 + (i >> 5);
        unsigned int v = 0;
        if (yy >= 0 && yy < IMG_H)
            v = g_hbits[(size_t)(imgbase + yy) * WPR + (i & 31)];
        se[i] = v;
    }
    const unsigned int lw = g_lbits[(size_t)row * WPR + lane];
    __syncthreads();

    // Vertical OR from smem
    unsigned int ew = 0;
#pragma unroll
    for (int dy = 0; dy < 15; dy++) ew |= se[(wid + dy) * WPR + lane];

    int cLab  = __popc(lw);
    int cEdge = __popc(ew);

    // Transpose: lane's pixel i (=4k+j) is word 4k+(lane>>3), nib 4*(lane&7)
    unsigned int mylw = 0, myew = 0;
    const int nsh = 4 * (lane & 7);
#pragma unroll
    for (int k = 0; k < 8; k++) {
        const int widx = 4 * k + (lane >> 3);
        mylw |= ((__shfl_sync(0xffffffffu, lw, widx) >> nsh) & 0xFu) << (4 * k);
        myew |= ((__shfl_sync(0xffffffffu, ew, widx) >> nsh) & 0xFu) << (4 * k);
    }

    // Compute: chunked loads (4 float4 in flight), low reg footprint
    float sAll = 0.f, sEdge = 0.f, sLab = 0.f;
    const float4* prow = (const float4*)(Pred + (size_t)row * IMG_W);

#pragma unroll 4
    for (int k = 0; k < 8; k++) {
        const float4 p4 = prow[k * 32 + lane];

#define PIX(pv, j)                                                 \
        {                                                          \
            const int bit = 4 * k + (j);                           \
            const bool tl = (mylw >> bit) & 1u;                    \
            const bool el = (myew >> bit) & 1u;                    \
            const float q  = tl ? (pv) : 1.0f - (pv);              \
            const float l2 = __log2f(q);                           \
            sAll += l2;                                            \
            if (el) sEdge += l2;                                   \
            if (tl) sLab  += l2;                                   \
        }
        PIX(p4.x, 0)
        PIX(p4.y, 1)
        PIX(p4.z, 2)
        PIX(p4.w, 3)
#undef PIX
    }

#pragma unroll
    for (int off = 16; off; off >>= 1) {
        sAll  += __shfl_xor_sync(0xffffffffu, sAll,  off);
        sEdge += __shfl_xor_sync(0xffffffffu, sEdge, off);
        sLab  += __shfl_xor_sync(0xffffffffu, sLab,  off);
    }
    cLab  = __reduce_add_sync(0xffffffffu, cLab);
    cEdge = __reduce_add_sync(0xffffffffu, cEdge);

    __shared__ float fs[3][8];
    __shared__ int   is[2][8];
    if (lane == 0) {
        fs[0][wid] = sAll; fs[1][wid] = sEdge; fs[2][wid] = sLab;
        is[0][wid] = cLab; is[1][wid] = cEdge;
    }
    __syncthreads();
    if (t == 0) {
        double bA = 0, bE = 0, bL = 0; int iL = 0, iE = 0;
#pragma unroll
        for (int i = 0; i < 8; i++) {
            bA += fs[0][i]; bE += fs[1][i]; bL += fs[2][i];
            iL += is[0][i]; iE += is[1][i];
        }
        atomicAdd(&g_sum[0], bA);
        atomicAdd(&g_sum[1], bE);
        atomicAdd(&g_sum[2], bL);
        atomicAdd(&g_cnt[0], iL);
        atomicAdd(&g_cnt[1], iE);
        __threadfence();
        if (atomicAdd(&g_done, 1) == (int)gridDim.x - 1) {
            g_done = 0;                                  // replay-deterministic
            const double N  = NTOT;
            const double nL = (double)g_cnt[0];          // label (E) count
            const double nE = (double)g_cnt[1];          // edge count
            const double sA = g_sum[0], sE2 = g_sum[1], sL = g_sum[2];
            const double wE = (1.0 - nL / N) * 1.0;
            const double wB = (1.0 - (nE - nL) / N) * 0.8;
            const double wT = (1.0 - (N - nE) / N) * 0.5;
            const double LN2 = 0.6931471805599453;
            out[0] = (float)(-LN2 * (wE * sL + wB * (sE2 - sL) + wT * (sA - sE2)) / N);
        }
    }
}

extern "C" void kernel_launch(void* const* d_in, const int* in_sizes, int n_in,
                              void* d_out, int out_size) {
    const float* Pred  = (const float*)d_in[0];
    const int*   label = (const int*)d_in[1];
    (void)in_sizes; (void)n_in; (void)out_size;

    pack_hor<<<NROWS / ROWS_PER_BLK, 256>>>(label);
    main_kernel<<<NROWS / 8, 256>>>(Pred, (float*)d_out);
}

// round 7
// speedup vs baseline: 1.3197x; 1.1565x over previous
#include <cuda_runtime.h>

#define BATCH 16
#define IMG_H 1024
#define IMG_W 1024
#define WPR   32                 // 32-bit words per row (1024/32)
#define NROWS (BATCH * IMG_H)
#define NTOT  ((double)BATCH * IMG_H * IMG_W)
#define ROWS_PER_BLK 8           // pack kernel rows/block
#define RPB 32                   // main kernel rows/block
#define NMAIN (NROWS / RPB)      // 512 main blocks

// Scratch (allocation-free: __device__ globals)
__device__ unsigned int g_lbits[NROWS * WPR];   // label bits, 2 MB
__device__ unsigned int g_hbits[NROWS * WPR];   // horizontal-OR (r=7) bits, 2 MB
__device__ double g_sum[3];                     // sums of lg2(q): All, Edge, Lab
__device__ int    g_cnt[2];                     // counts: Lab, Edge
__device__ int    g_done;                       // arrival counter (reset each run)

// ---------------------------------------------------------------------------
// Kernel A: 256 threads / 8 rows. 8 int4 loads front-batched (MLP=8, the
// measured-best config: 13.8us @ 62% DRAM). Shuffle-fold to words, then
// horizontal radius-7 OR via 64-bit shift doubling.
// ---------------------------------------------------------------------------
__global__ void __launch_bounds__(256) pack_hor(const int* __restrict__ label) {
    __shared__ unsigned int sw[ROWS_PER_BLK * WPR];
    const int t    = threadIdx.x;
    const int lane = t & 31;

    const int4* lab4 = (const int4*)label + (size_t)blockIdx.x * (ROWS_PER_BLK * WPR * 8);
    int4 v[8];
#pragma unroll
    for (int k = 0; k < 8; k++) v[k] = lab4[k * 256 + t];

    if (blockIdx.x == 0 && t < 3) {
        g_sum[t] = 0.0;
        if (t < 2) g_cnt[t] = 0;
    }

#pragma unroll
    for (int k = 0; k < 8; k++) {
        unsigned int nib = (unsigned)v[k].x | ((unsigned)v[k].y << 1)
                         | ((unsigned)v[k].z << 2) | ((unsigned)v[k].w << 3);
        unsigned int val = nib << (4 * (lane & 7));
        val |= __shfl_xor_sync(0xffffffffu, val, 1);
        val |= __shfl_xor_sync(0xffffffffu, val, 2);
        val |= __shfl_xor_sync(0xffffffffu, val, 4);
        if ((lane & 7) == 0) sw[(k * 256 + t) >> 3] = val;
    }
    __syncthreads();

    const int w = t & 31;
    const unsigned int wl = (w > 0)       ? sw[t - 1] : 0u;
    const unsigned int wc = sw[t];
    const unsigned int wr = (w < WPR - 1) ? sw[t + 1] : 0u;
    unsigned long long a = (unsigned long long)wc | ((unsigned long long)wr << 32);
    a |= a >> 1; a |= a >> 2; a |= a >> 4;              // OR of px x..x+7
    unsigned long long c = (unsigned long long)wl | ((unsigned long long)wc << 32);
    c |= c << 1; c |= c << 2; c |= c << 4;              // OR of px x-7..x
    const size_t gidx = (size_t)blockIdx.x * (ROWS_PER_BLK * WPR) + t;
    g_lbits[gidx] = wc;
    g_hbits[gidx] = (unsigned int)a | (unsigned int)(c >> 32);
}

// ---------------------------------------------------------------------------
// Kernel B: 32 rows/block, 512 blocks, 256 threads. Warp w processes local
// rows 4w..4w+3 sequentially — smem fill/BAR and reduction tail paid once per
// 4 rows. Edge words for all 4 rows from one 18-load shared-window OR.
// ---------------------------------------------------------------------------
__global__ void __launch_bounds__(256) main_kernel(const float* __restrict__ Pred,
                                                   float* __restrict__ out) {
    __shared__ unsigned int se[(RPB + 14) * WPR];       // 46 hbits rows
    const int t    = threadIdx.x;
    const int lane = t & 31;
    const int wid  = t >> 5;
    const int row0 = blockIdx.x * RPB;                  // 32 rows, never spans images
    const int y0   = row0 & (IMG_H - 1);
    const int imgbase = row0 - y0;

    // Cooperative fill: hbits rows y0-7 .. y0+38, clipped (1472 words)
    for (int i = t; i < (RPB + 14) * WPR; i += 256) {
        const int yy = y0 - 7 + (i >> 5);
        unsigned int v = 0;
        if (yy >= 0 && yy < IMG_H)
            v = g_hbits[(size_t)(imgbase + yy) * WPR + (i & 31)];
        se[i] = v;
    }
    __syncthreads();

    // Vertical OR for 4 consecutive rows from one window: rows base..base+3
    // need smem rows base..base+17 (smem idx r covers global y0+r-7).
    const int base = 4 * wid;
    unsigned int s[18];
#pragma unroll
    for (int d = 0; d < 18; d++) s[d] = se[(base + d) * WPR + lane];
    unsigned int common = s[3];
#pragma unroll
    for (int d = 4; d <= 14; d++) common |= s[d];
    unsigned int ewr[4];
    ewr[0] = common | s[0] | s[1] | s[2];
    ewr[1] = common | s[1] | s[2] | s[15];
    ewr[2] = common | s[2] | s[15] | s[16];
    ewr[3] = common | s[15] | s[16] | s[17];

    float sAll = 0.f, sEdge = 0.f, sLab = 0.f;
    int cLab = 0, cEdge = 0;
    const int nsh = 4 * (lane & 7);

#pragma unroll
    for (int j = 0; j < 4; j++) {
        const int row = row0 + base + j;
        const unsigned int lw = g_lbits[(size_t)row * WPR + lane];
        const unsigned int ew = ewr[j];

        // Front-batched coalesced Pred loads for this row (MLP=8)
        const float4* prow = (const float4*)(Pred + (size_t)row * IMG_W);
        float4 p[8];
#pragma unroll
        for (int k = 0; k < 8; k++) p[k] = prow[k * 32 + lane];

        cLab  += __popc(lw);
        cEdge += __popc(ew);

        // Transpose: lane's pixel i (=4k+jj) is word 4k+(lane>>3), nib 4*(lane&7)
        unsigned int mylw = 0, myew = 0;
#pragma unroll
        for (int k = 0; k < 8; k++) {
            const int widx = 4 * k + (lane >> 3);
            mylw |= ((__shfl_sync(0xffffffffu, lw, widx) >> nsh) & 0xFu) << (4 * k);
            myew |= ((__shfl_sync(0xffffffffu, ew, widx) >> nsh) & 0xFu) << (4 * k);
        }

#define PIX(pv, bit)                                               \
        {                                                          \
            const bool tl = (mylw >> (bit)) & 1u;                  \
            const bool el = (myew >> (bit)) & 1u;                  \
            const float q  = tl ? (pv) : 1.0f - (pv);              \
            const float l2 = __log2f(q);                           \
            sAll += l2;                                            \
            if (el) sEdge += l2;                                   \
            if (tl) sLab  += l2;                                   \
        }
#pragma unroll
        for (int k = 0; k < 8; k++) {
            PIX(p[k].x, 4 * k + 0)
            PIX(p[k].y, 4 * k + 1)
            PIX(p[k].z, 4 * k + 2)
            PIX(p[k].w, 4 * k + 3)
        }
#undef PIX
    }

    // One reduction tail per 4 rows
#pragma unroll
    for (int off = 16; off; off >>= 1) {
        sAll  += __shfl_xor_sync(0xffffffffu, sAll,  off);
        sEdge += __shfl_xor_sync(0xffffffffu, sEdge, off);
        sLab  += __shfl_xor_sync(0xffffffffu, sLab,  off);
    }
    cLab  = __reduce_add_sync(0xffffffffu, cLab);
    cEdge = __reduce_add_sync(0xffffffffu, cEdge);

    __shared__ float fs[3][8];
    __shared__ int   is[2][8];
    if (lane == 0) {
        fs[0][wid] = sAll; fs[1][wid] = sEdge; fs[2][wid] = sLab;
        is[0][wid] = cLab; is[1][wid] = cEdge;
    }
    __syncthreads();
    if (t == 0) {
        double bA = 0, bE = 0, bL = 0; int iL = 0, iE = 0;
#pragma unroll
        for (int i = 0; i < 8; i++) {
            bA += fs[0][i]; bE += fs[1][i]; bL += fs[2][i];
            iL += is[0][i]; iE += is[1][i];
        }
        atomicAdd(&g_sum[0], bA);
        atomicAdd(&g_sum[1], bE);
        atomicAdd(&g_sum[2], bL);
        atomicAdd(&g_cnt[0], iL);
        atomicAdd(&g_cnt[1], iE);
        __threadfence();
        if (atomicAdd(&g_done, 1) == (int)gridDim.x - 1) {
            g_done = 0;                                  // replay-deterministic
            const double N  = NTOT;
            const double nL = (double)g_cnt[0];          // label (E) count
            const double nE = (double)g_cnt[1];          // edge count
            const double sA = g_sum[0], sE2 = g_sum[1], sL = g_sum[2];
            const double wE = (1.0 - nL / N) * 1.0;
            const double wB = (1.0 - (nE - nL) / N) * 0.8;
            const double wT = (1.0 - (N - nE) / N) * 0.5;
            const double LN2 = 0.6931471805599453;
            out[0] = (float)(-LN2 * (wE * sL + wB * (sE2 - sL) + wT * (sA - sE2)) / N);
        }
    }
}

extern "C" void kernel_launch(void* const* d_in, const int* in_sizes, int n_in,
                              void* d_out, int out_size) {
    const float* Pred  = (const float*)d_in[0];
    const int*   label = (const int*)d_in[1];
    (void)in_sizes; (void)n_in; (void)out_size;

    pack_hor<<<NROWS / ROWS_PER_BLK, 256>>>(label);
    main_kernel<<<NMAIN, 256>>>(Pred, (float*)d_out);
}

// round 8
// speedup vs baseline: 1.4045x; 1.0643x over previous
#include <cuda_runtime.h>

#define BATCH 16
#define IMG_H 1024
#define IMG_W 1024
#define WPR   32                 // 32-bit words per row (1024/32)
#define NROWS (BATCH * IMG_H)
#define NTOT  ((double)BATCH * IMG_H * IMG_W)
#define ROWS_PER_BLK 8           // pack kernel rows/block
#define RPB 16                   // main kernel rows/block
#define MWARPS 4                 // main kernel warps/block
#define NMAIN (NROWS / RPB)      // 1024 main blocks
#define ROWPAD 4608              // staged row bytes: 4096 * 9/8 (bank-conflict pad)

// Scratch (allocation-free: __device__ globals)
__device__ unsigned int g_lbits[NROWS * WPR];   // label bits, 2 MB
__device__ unsigned int g_hbits[NROWS * WPR];   // horizontal-OR (r=7) bits, 2 MB
__device__ double g_sum[3];                     // sums of lg2(q): All, Edge, Lab
__device__ int    g_cnt[2];                     // counts: Lab, Edge
__device__ int    g_done;                       // arrival counter (reset each run)

static __device__ __forceinline__ unsigned su32(const void* p) {
    return (unsigned)__cvta_generic_to_shared(p);
}
static __device__ __forceinline__ void cpa16(unsigned smem, const void* g) {
    asm volatile("cp.async.cg.shared.global [%0], [%1], 16;\n" :: "r"(smem), "l"(g));
}

// ---------------------------------------------------------------------------
// Kernel A: unchanged (measured 13.8us @ 62% DRAM). 256 threads / 8 rows,
// front-batched int4 loads, shuffle-fold, horizontal radius-7 OR.
// ---------------------------------------------------------------------------
__global__ void __launch_bounds__(256) pack_hor(const int* __restrict__ label) {
    __shared__ unsigned int sw[ROWS_PER_BLK * WPR];
    const int t    = threadIdx.x;
    const int lane = t & 31;

    const int4* lab4 = (const int4*)label + (size_t)blockIdx.x * (ROWS_PER_BLK * WPR * 8);
    int4 v[8];
#pragma unroll
    for (int k = 0; k < 8; k++) v[k] = lab4[k * 256 + t];

    if (blockIdx.x == 0 && t < 3) {
        g_sum[t] = 0.0;
        if (t < 2) g_cnt[t] = 0;
    }

#pragma unroll
    for (int k = 0; k < 8; k++) {
        unsigned int nib = (unsigned)v[k].x | ((unsigned)v[k].y << 1)
                         | ((unsigned)v[k].z << 2) | ((unsigned)v[k].w << 3);
        unsigned int val = nib << (4 * (lane & 7));
        val |= __shfl_xor_sync(0xffffffffu, val, 1);
        val |= __shfl_xor_sync(0xffffffffu, val, 2);
        val |= __shfl_xor_sync(0xffffffffu, val, 4);
        if ((lane & 7) == 0) sw[(k * 256 + t) >> 3] = val;
    }
    __syncthreads();

    const int w = t & 31;
    const unsigned int wl = (w > 0)       ? sw[t - 1] : 0u;
    const unsigned int wc = sw[t];
    const unsigned int wr = (w < WPR - 1) ? sw[t + 1] : 0u;
    unsigned long long a = (unsigned long long)wc | ((unsigned long long)wr << 32);
    a |= a >> 1; a |= a >> 2; a |= a >> 4;
    unsigned long long c = (unsigned long long)wl | ((unsigned long long)wc << 32);
    c |= c << 1; c |= c << 2; c |= c << 4;
    const size_t gidx = (size_t)blockIdx.x * (ROWS_PER_BLK * WPR) + t;
    g_lbits[gidx] = wc;
    g_hbits[gidx] = (unsigned int)a | (unsigned int)(c >> 32);
}

// ---------------------------------------------------------------------------
// Kernel B: 16 rows/block, 4 warps; warp w owns rows 4w..4w+3, double-
// buffering each row of Pred into padded smem via cp.async (zero reg cost,
// decouples in-flight bytes from occupancy). Compute reads conflict-free
// LDS.128; mask word for lane L is simply word L (no transpose shuffles).
//
// smem row layout: pixel-float4 g at byte 16*g + 16*(g>>3) (16B gap per 128B)
//   write (coalesced gmem): g = 32j+L  -> 576j + 16L + 16*(L>>3)
//   read  (per-lane):       g = 8L+j8  -> 144L + 16*j8   (conflict-free)
// ---------------------------------------------------------------------------
__global__ void __launch_bounds__(128) main_kernel(const float* __restrict__ Pred,
                                                   float* __restrict__ out) {
    __shared__ __align__(16) char ring[MWARPS][2][ROWPAD];   // 36.9 KB
    __shared__ unsigned int se[(RPB + 14) * WPR];            // 3.75 KB
    const int t    = threadIdx.x;
    const int lane = t & 31;
    const int wid  = t >> 5;
    const int row0 = blockIdx.x * RPB;                       // never spans images
    const int y0   = row0 & (IMG_H - 1);
    const int imgbase = row0 - y0;
    const int base = 4 * wid;                                // warp's first local row

    // Kick off the async pipeline immediately: rows base+0, base+1
    const unsigned rb[2] = { su32(&ring[wid][0][0]), su32(&ring[wid][1][0]) };
    const unsigned doff  = 16 * lane + 16 * (lane >> 3);
#pragma unroll
    for (int b = 0; b < 2; b++) {
        const char* gp = (const char*)(Pred + (size_t)(row0 + base + b) * IMG_W);
#pragma unroll
        for (int j = 0; j < 8; j++)
            cpa16(rb[b] + 576 * j + doff, gp + 512 * j + 16 * lane);
        asm volatile("cp.async.commit_group;\n" ::: "memory");
    }

    // Label words for the 4 rows (coalesced, front-batched)
    unsigned int lwr[4];
#pragma unroll
    for (int j = 0; j < 4; j++)
        lwr[j] = g_lbits[(size_t)(row0 + base + j) * WPR + lane];

    // Cooperative fill: hbits rows y0-7 .. y0+RPB+6, clipped (960 words)
    for (int i = t; i < (RPB + 14) * WPR; i += 128) {
        const int yy = y0 - 7 + (i >> 5);
        unsigned int v = 0;
        if (yy >= 0 && yy < IMG_H)
            v = g_hbits[(size_t)(imgbase + yy) * WPR + (i & 31)];
        se[i] = v;
    }
    __syncthreads();

    // Vertical OR windows: row base+j needs se rows base+j .. base+j+14
    unsigned int common = 0;
#pragma unroll
    for (int d = 3; d <= 14; d++) common |= se[(base + d) * WPR + lane];
    unsigned int ewr[4];
    {
        const unsigned s0  = se[(base + 0)  * WPR + lane];
        const unsigned s1  = se[(base + 1)  * WPR + lane];
        const unsigned s2  = se[(base + 2)  * WPR + lane];
        const unsigned s15 = se[(base + 15) * WPR + lane];
        const unsigned s16 = se[(base + 16) * WPR + lane];
        const unsigned s17 = se[(base + 17) * WPR + lane];
        ewr[0] = common | s0  | s1  | s2;
        ewr[1] = common | s1  | s2  | s15;
        ewr[2] = common | s2  | s15 | s16;
        ewr[3] = common | s15 | s16 | s17;
    }

    float sAll = 0.f, sEdge = 0.f, sLab = 0.f;
    int cLab = 0, cEdge = 0;

#pragma unroll
    for (int j = 0; j < 4; j++) {
        // Row j staged? (outstanding groups: {Pj, Pj+1} for j<3, {P3} at j=3)
        if (j < 3) asm volatile("cp.async.wait_group 1;\n" ::: "memory");
        else       asm volatile("cp.async.wait_group 0;\n" ::: "memory");
        __syncwarp();

        const unsigned int lw = lwr[j];
        const unsigned int ew = ewr[j];
        cLab  += __popc(lw);
        cEdge += __popc(ew);

        const char* buf = &ring[wid][j & 1][0];
#pragma unroll
        for (int j8 = 0; j8 < 8; j8++) {
            const float4 v = *(const float4*)(buf + 144 * lane + 16 * j8);
#define PIX(pv, bit)                                               \
            {                                                      \
                const bool tl = (lw >> (bit)) & 1u;                \
                const bool el = (ew >> (bit)) & 1u;                \
                const float q  = tl ? (pv) : 1.0f - (pv);          \
                const float l2 = __log2f(q);                       \
                sAll += l2;                                        \
                if (el) sEdge += l2;                               \
                if (tl) sLab  += l2;                               \
            }
            PIX(v.x, 4 * j8 + 0)
            PIX(v.y, 4 * j8 + 1)
            PIX(v.z, 4 * j8 + 2)
            PIX(v.w, 4 * j8 + 3)
#undef PIX
        }

        // Reuse this buffer for row j+2 (all lanes done reading first)
        if (j < 2) {
            __syncwarp();
            const char* gp = (const char*)(Pred + (size_t)(row0 + base + j + 2) * IMG_W);
#pragma unroll
            for (int k = 0; k < 8; k++)
                cpa16(rb[j & 1] + 576 * k + doff, gp + 512 * k + 16 * lane);
            asm volatile("cp.async.commit_group;\n" ::: "memory");
        }
    }

    // Reduction: warp, then block (4 warps), then fused finalize
#pragma unroll
    for (int off = 16; off; off >>= 1) {
        sAll  += __shfl_xor_sync(0xffffffffu, sAll,  off);
        sEdge += __shfl_xor_sync(0xffffffffu, sEdge, off);
        sLab  += __shfl_xor_sync(0xffffffffu, sLab,  off);
    }
    cLab  = __reduce_add_sync(0xffffffffu, cLab);
    cEdge = __reduce_add_sync(0xffffffffu, cEdge);

    __shared__ float fs[3][MWARPS];
    __shared__ int   is[2][MWARPS];
    if (lane == 0) {
        fs[0][wid] = sAll; fs[1][wid] = sEdge; fs[2][wid] = sLab;
        is[0][wid] = cLab; is[1][wid] = cEdge;
    }
    __syncthreads();
    if (t == 0) {
        double bA = 0, bE = 0, bL = 0; int iL = 0, iE = 0;
#pragma unroll
        for (int i = 0; i < MWARPS; i++) {
            bA += fs[0][i]; bE += fs[1][i]; bL += fs[2][i];
            iL += is[0][i]; iE += is[1][i];
        }
        atomicAdd(&g_sum[0], bA);
        atomicAdd(&g_sum[1], bE);
        atomicAdd(&g_sum[2], bL);
        atomicAdd(&g_cnt[0], iL);
        atomicAdd(&g_cnt[1], iE);
        __threadfence();
        if (atomicAdd(&g_done, 1) == (int)gridDim.x - 1) {
            g_done = 0;                                  // replay-deterministic
            const double N  = NTOT;
            const double nL = (double)g_cnt[0];          // label (E) count
            const double nE = (double)g_cnt[1];          // edge count
            const double sA = g_sum[0], sE2 = g_sum[1], sL = g_sum[2];
            const double wE = (1.0 - nL / N) * 1.0;
            const double wB = (1.0 - (nE - nL) / N) * 0.8;
            const double wT = (1.0 - (N - nE) / N) * 0.5;
            const double LN2 = 0.6931471805599453;
            out[0] = (float)(-LN2 * (wE * sL + wB * (sE2 - sL) + wT * (sA - sE2)) / N);
        }
    }
}

extern "C" void kernel_launch(void* const* d_in, const int* in_sizes, int n_in,
                              void* d_out, int out_size) {
    const float* Pred  = (const float*)d_in[0];
    const int*   label = (const int*)d_in[1];
    (void)in_sizes; (void)n_in; (void)out_size;

    pack_hor<<<NROWS / ROWS_PER_BLK, 256>>>(label);
    main_kernel<<<NMAIN, 128>>>(Pred, (float*)d_out);
}